// round 11
// baseline (speedup 1.0000x reference)
#include <cuda_runtime.h>

// B=8192, D=512, NUM_CLASSES=90, K=8
// Numerics (validated R9/R10): per dot, NEON VF4xIC2 structure:
//   8 independent serial FMA chains, chain j covers elements 8i+j (i=0..63);
//   combine v_e = fadd(chain_e, chain_{e+4}); dot = fadd(fadd(v0,v1),fadd(v2,v3));
//   d = fadd(1,dot). Epilogue f32 per-op rounded, k ascending. Batch sums double.
// Single fused kernel: class-grouped SMEM reuse + last-block final reduction.

#define NUM_CLASSES 90
#define CHUNKS      16
#define CHUNK_B     512
#define NBLK        (NUM_CLASSES * CHUNKS)   // 1440
#define THREADS     192
#define NWARPS      6
#define SLOTS       12
#define CPAD        516    // ≡4 (mod 32): 16 chain addrs tile banks exactly 2x
#define XPAD        520    // ≡8 (mod 32): 4 distinct x addrs, conflict-free

__device__ double   g_partials[NBLK];
__device__ unsigned g_count = 0;

__global__ __launch_bounds__(THREADS) void loss_main(
    const float* __restrict__ x,
    const float* __restrict__ centers,
    const int* __restrict__ labels,
    float* __restrict__ out)
{
    __shared__ float    cs[8 * CPAD];
    __shared__ float    xsm[SLOTS * XPAD];
    __shared__ int      list[CHUNK_B];
    __shared__ unsigned gmask[16];
    __shared__ int      gbase[16];
    __shared__ int      s_n;
    __shared__ float    dk[SLOTS][8];
    __shared__ double   red[NWARPS];
    __shared__ int      s_last;

    const int tid    = threadIdx.x;
    const int cls    = blockIdx.x / CHUNKS;
    const int chunk  = blockIdx.x % CHUNKS;
    const int base_b = chunk * CHUNK_B;
    const int warp   = tid >> 5;
    const int lane   = tid & 31;

    // ---- stage this class's 8 center rows (coalesced float4) ----
    const float4* __restrict__ gc4 =
        reinterpret_cast<const float4*>(centers + (size_t)cls * 8 * 512);
    for (int u = tid; u < 1024; u += THREADS) {
        int row = u >> 7, f4 = u & 127;
        float4 v = gc4[row * 128 + f4];
        *reinterpret_cast<float4*>(&cs[row * CPAD + f4 * 4]) = v;
    }

    // ---- deterministic scan for label==cls in this chunk ----
    for (int g = warp; g < 16; g += NWARPS) {
        int idx = base_b + g * 32 + lane;
        unsigned bal = __ballot_sync(0xFFFFFFFFu, labels[idx] == cls);
        if (lane == 0) gmask[g] = bal;
    }
    __syncthreads();
    if (warp == 0 && lane < 16) {
        int cnt = __popc(gmask[lane]);
        int inc = cnt;
#pragma unroll
        for (int off = 1; off < 16; off <<= 1) {
            int o = __shfl_up_sync(0x0000FFFFu, inc, off);
            if (lane >= off) inc += o;
        }
        gbase[lane] = inc - cnt;
        if (lane == 15) s_n = inc;
    }
    __syncthreads();
    for (int g = warp; g < 16; g += NWARPS) {
        unsigned m = gmask[g];
        if ((m >> lane) & 1u)
            list[gbase[g] + __popc(m & ((1u << lane) - 1u))] = g * 32 + lane;
    }
    __syncthreads();

    const int n  = s_n;
    const int nr = (n + SLOTS - 1) / SLOTS;
    double bsum = 0.0;

    const int s     = tid >> 4;       // slot 0..11
    const int k     = (tid >> 1) & 7;
    const int h     = tid & 1;        // 0: chains 8i+0..3, 1: chains 8i+4..7
    const int tslot = tid & 15;

    for (int r = 0; r < nr; ++r) {
        const int si = r * SLOTS + s;
        if (si < n) {   // stage x row (16 threads/slot, coalesced)
            int b = base_b + list[si];
            const float4* __restrict__ x4 =
                reinterpret_cast<const float4*>(x + (size_t)b * 512);
#pragma unroll
            for (int v = 0; v < 8; ++v) {
                int f4 = tslot + 16 * v;
                *reinterpret_cast<float4*>(&xsm[s * XPAD + f4 * 4]) = x4[f4];
            }
        }
        __syncthreads();

        // chain only for warps with at least one active slot (warp-uniform)
        if (r * SLOTS + (warp << 1) < n) {
            float4 acc = make_float4(0.f, 0.f, 0.f, 0.f);
            const float* xb = &xsm[s * XPAD + h * 4];
            const float* cb = &cs[k * CPAD + h * 4];
#pragma unroll 16
            for (int i = 0; i < 64; ++i) {
                float4 xv = *reinterpret_cast<const float4*>(xb + i * 8);
                float4 cv = *reinterpret_cast<const float4*>(cb + i * 8);
                acc.x = fmaf(xv.x, cv.x, acc.x);
                acc.y = fmaf(xv.y, cv.y, acc.y);
                acc.z = fmaf(xv.z, cv.z, acc.z);
                acc.w = fmaf(xv.w, cv.w, acc.w);
            }
            float px = __shfl_xor_sync(0xFFFFFFFFu, acc.x, 1);
            float py = __shfl_xor_sync(0xFFFFFFFFu, acc.y, 1);
            float pz = __shfl_xor_sync(0xFFFFFFFFu, acc.z, 1);
            float pw = __shfl_xor_sync(0xFFFFFFFFu, acc.w, 1);
            float v0 = __fadd_rn(acc.x, px);
            float v1 = __fadd_rn(acc.y, py);
            float v2 = __fadd_rn(acc.z, pz);
            float v3 = __fadd_rn(acc.w, pw);
            float dot = __fadd_rn(__fadd_rn(v0, v1), __fadd_rn(v2, v3));
            float d = __fadd_rn(1.0f, dot);
            if (h == 0 && si < n) dk[s][k] = d;
        }
        __syncthreads();

        // parallel per-sample epilogue (exact per-op f32 rounding, k ascending)
        int cnt = n - r * SLOTS;
        if (cnt > SLOTS) cnt = SLOTS;
        if (tid < cnt) {
            float dl[8];
#pragma unroll
            for (int j = 0; j < 8; ++j) dl[j] = dk[tid][j];
            float s1 = dl[0];
#pragma unroll
            for (int j = 1; j < 8; ++j) s1 = __fadd_rn(s1, dl[j]);
            float accw = 0.f;
#pragma unroll
            for (int j = 0; j < 8; ++j) {
                float w = __fdiv_rn(dl[j], s1);
                float p = __fmul_rn(w, dl[j]);
                accw = __fadd_rn(accw, p);
            }
            bsum += (double)accw;
        }
        __syncthreads();
    }

    // ---- deterministic block reduction of bsum (double) ----
#pragma unroll
    for (int m = 16; m >= 1; m >>= 1)
        bsum += __shfl_xor_sync(0xFFFFFFFFu, bsum, m);
    if (lane == 0) red[warp] = bsum;
    __syncthreads();
    if (tid == 0) {
        double t = 0.0;
#pragma unroll
        for (int j = 0; j < NWARPS; ++j) t += red[j];
        g_partials[blockIdx.x] = t;
        __threadfence();
        unsigned old = atomicInc(&g_count, NBLK - 1);   // wraps to 0 -> auto reset
        s_last = (old == NBLK - 1);
    }
    __syncthreads();

    // ---- last block folds all partials (fixed order -> deterministic) ----
    if (s_last) {
        double v = 0.0;
        for (int i = tid; i < NBLK; i += THREADS)
            v += __ldcg(&g_partials[i]);
#pragma unroll
        for (int m = 16; m >= 1; m >>= 1)
            v += __shfl_xor_sync(0xFFFFFFFFu, v, m);
        if (lane == 0) red[warp] = v;
        __syncthreads();
        if (tid == 0) {
            double t = 0.0;
#pragma unroll
            for (int j = 0; j < NWARPS; ++j) t += red[j];
            out[0] = (float)(t * (1.0 / 8192.0));
        }
    }
}

extern "C" void kernel_launch(void* const* d_in, const int* in_sizes, int n_in,
                              void* d_out, int out_size)
{
    const float* x       = (const float*)d_in[0];
    const float* centers = (const float*)d_in[1];
    const int*   labels  = (const int*)d_in[2];
    float*       out     = (float*)d_out;

    loss_main<<<NBLK, THREADS>>>(x, centers, labels, out);
}